// round 9
// baseline (speedup 1.0000x reference)
#include <cuda_runtime.h>
#include <math.h>

#define NSPIN 256
#define FDIM  64
#define BATCH 64
#define NITER 40
#define TOLF  1e-4f
#define JS_STRIDE 260      // [128][260] floats: conflict-free LDS
#define AS_STRIDE 68       // [256][68] floats
#define NBLK   136u

// -------------------- device scratch (no runtime allocation) --------------------
__device__ float g_J[NSPIN * NSPIN];
__device__ float g_U1[BATCH * NSPIN * FDIM];            // J h (pair handoff)
__device__ float g_mAA0[BATCH][2];                      // ||h||^2 partials (by rt)
__device__ float g_mAC0[BATCH][2];                      // <h,u1> partials
__device__ float g_mAA1[BATCH][2];                      // ||u1||^2 partials
__device__ float g_mAC1[BATCH][2];                      // <u1,u2> partials
__device__ float g_mCC [BATCH][2];                      // ||u2||^2 partials
__device__ float g_tAA[4];                              // tr(J^2) partials (by ct)
__device__ float g_tAC[2][4];                           // tr(J^3) partials
__device__ float g_tCC[2][4];                           // tr(J^4) partials
__device__ unsigned g_bar;                              // monotonic grid ticket
__device__ unsigned g_pair[BATCH];                      // monotonic pair tickets

#define VL(x) (*(volatile float*)&(x))

// -------------------- helpers --------------------
__device__ __forceinline__ unsigned long long dup2(float a) {
    unsigned long long r;
    asm("mov.b64 %0, {%1, %1};" : "=l"(r) : "f"(a));
    return r;
}
__device__ __forceinline__ void fma2(unsigned long long& acc, unsigned long long a,
                                     unsigned long long b) {
    asm("fma.rn.f32x2 %0, %1, %2, %3;" : "=l"(acc) : "l"(a), "l"(b), "l"(acc));
}
__device__ __forceinline__ float lo32(unsigned long long v) {
    return __uint_as_float((unsigned)(v & 0xffffffffull));
}
__device__ __forceinline__ float hi32(unsigned long long v) {
    return __uint_as_float((unsigned)(v >> 32));
}

// grid-wide barrier: monotonic tickets, replay-safe. Valid: 136 blocks co-resident.
__device__ __forceinline__ void grid_barrier() {
    __threadfence();
    __syncthreads();
    if (threadIdx.x == 0) {
        unsigned old = atomicAdd(&g_bar, 1u);
        unsigned target = old - (old % NBLK) + NBLK;
        while ((int)(*(volatile unsigned*)&g_bar - target) < 0) __nanosleep(32);
    }
    __syncthreads();
}

// block reduce for 512 threads (16 warps)
__device__ __forceinline__ float blockReduceSum(float v, float* scratch) {
    #pragma unroll
    for (int o = 16; o > 0; o >>= 1) v += __shfl_down_sync(0xffffffffu, v, o);
    int lane = threadIdx.x & 31, w = threadIdx.x >> 5;
    if (lane == 0) scratch[w] = v;
    __syncthreads();
    float r = 0.f;
    if (w == 0) {
        r = (lane < 16) ? scratch[lane] : 0.f;
        #pragma unroll
        for (int o = 8; o > 0; o >>= 1) r += __shfl_down_sync(0xffffffffu, r, o);
    }
    __syncthreads();
    return r;   // valid in thread 0
}

// -------------------- inner gemm over k range [k0,k1), accumulating ------------
__device__ __forceinline__ void gemm_range(const float* jr0, const float* jr1,
                                           const float* bcol, int k0, int k1,
                                           unsigned long long acc[2][4]) {
    #pragma unroll 4
    for (int kk = k0; kk < k1; kk += 4) {
        float4 ja = *(const float4*)&jr0[kk];
        float4 jb = *(const float4*)&jr1[kk];
        #pragma unroll
        for (int u = 0; u < 4; ++u) {
            ulonglong2 b0 = *(const ulonglong2*)&bcol[(kk + u) * AS_STRIDE];
            ulonglong2 b1 = *(const ulonglong2*)&bcol[(kk + u) * AS_STRIDE + 4];
            float jav = (u == 0) ? ja.x : (u == 1) ? ja.y : (u == 2) ? ja.z : ja.w;
            float jbv = (u == 0) ? jb.x : (u == 1) ? jb.y : (u == 2) ? jb.z : jb.w;
            unsigned long long a0 = dup2(jav);
            unsigned long long a1 = dup2(jbv);
            fma2(acc[0][0], a0, b0.x); fma2(acc[0][1], a0, b0.y);
            fma2(acc[0][2], a0, b1.x); fma2(acc[0][3], a0, b1.y);
            fma2(acc[1][0], a1, b0.x); fma2(acc[1][1], a1, b0.y);
            fma2(acc[1][2], a1, b1.x); fma2(acc[1][3], a1, b1.y);
        }
    }
}

// -------------------- fp32 Newton + phi + afe tail (last arrival) --------------
__device__ void newton_tail(int b, float* out, int out_size) {
    float m0 = VL(g_mAA0[b][0]) + VL(g_mAA0[b][1]);
    float m1 = VL(g_mAC0[b][0]) + VL(g_mAC0[b][1]);
    float m2 = VL(g_mAA1[b][0]) + VL(g_mAA1[b][1]);
    float m3 = VL(g_mAC1[b][0]) + VL(g_mAC1[b][1]);
    float m4 = VL(g_mCC [b][0]) + VL(g_mCC [b][1]);

    float tp2 = 0.f, tp3 = 0.f, tp4 = 0.f;
    #pragma unroll
    for (int q = 0; q < 4; q++) tp2 += VL(g_tAA[q]);
    #pragma unroll
    for (int r = 0; r < 2; r++)
        #pragma unroll
        for (int q = 0; q < 4; q++) { tp3 += VL(g_tAC[r][q]); tp4 += VL(g_tCC[r][q]); }

    const float cSb2 = 3.f * tp2, cSb3 = 4.f * tp3, cSb4 = 5.f * tp4;
    const float cQb0 = m0, cQb1 = 2.f*m1, cQb2 = 3.f*m2, cQb3 = 4.f*m3, cQb4 = 5.f*m4;
    const float cQc0 = m0, cQc1 = 3.f*m1, cQc2 = 6.f*m2, cQc3 = 10.f*m3, cQc4 = 15.f*m4;

    float t = 1.0f;
    for (int it = 0; it < NITER; ++it) {
        float xv = 1.0f / t;
        float Sa = (((tp4 * xv + tp3) * xv + tp2) * xv) * xv + 256.f;
        float Sb = (((cSb4 * xv + cSb3) * xv + cSb2) * xv) * xv + 256.f;
        float Qb = (((cQb4 * xv + cQb3) * xv + cQb2) * xv + cQb1) * xv + cQb0;
        float Qc = (((cQc4 * xv + cQc3) * xv + cQc2) * xv + cQc1) * xv + cQc0;
        float s1 = xv * Sa;
        float s2 = xv * xv * Sb;
        float q2 = xv * xv * Qb;
        float q3 = xv * xv * xv * Qc;
        float g  = 256.f - 0.5f * s1 - q2 * (1.f / 256.f);
        if (fabsf(g) <= TOLF) break;      // reference's update is 0 from here on
        float gp = 0.5f * s2 + q3 * (1.f / 128.f);
        t -= g / gp;
    }

    float xv = 1.0f / t;
    float Qa = ((((m4 * xv + m3) * xv + m2) * xv + m1) * xv + m0);
    float q1 = xv * Qa;
    float lds = ((tp4 * 0.25f * xv + tp3 * (1.f / 3.f)) * xv + tp2 * 0.5f) * xv * xv;
    float logdet = 256.f * __logf(t) - lds;
    float phi = 256.f * t - 0.5f * logdet + q1 * (1.f / 256.f);
    float afe = -(0.57236494292f + phi * (1.f / 256.f));   // 0.5*log(pi) + phi/N

    out[b] = afe;
    if (out_size >= 2 * BATCH) out[BATCH + b] = t;
}

// -------------------- the single fused kernel ----------------------------------
__global__ void __launch_bounds__(512, 1)
fused_kernel(const float* __restrict__ x, const float* __restrict__ Jr,
             float* __restrict__ out, int out_size) {
    extern __shared__ float sh[];
    float* Js = sh;                               // [128][JS_STRIDE]
    float* As = sh + 128 * JS_STRIDE;             // [256][AS_STRIDE]
    __shared__ float scratch[16];
    __shared__ unsigned islast;

    const int bid = blockIdx.x;
    const int tid = threadIdx.x;
    const bool isH = (bid < 128);

    int b = 0, rt, ct;
    if (isH) { b = bid >> 1; rt = bid & 1; ct = 0; }
    else     { int t = bid - 128; rt = t >> 2; ct = t & 3; }
    const int row0 = rt * 128;
    const int col0 = ct * 64;

    // ---- phase 0: build J once, cooperatively (2 rows per H block) ----
    if (isH) {
        int r = bid * 2 + (tid >> 8);
        int j = tid & 255;
        float v = (r == j) ? 0.f : 0.5f * (Jr[r * NSPIN + j] + Jr[j * NSPIN + r]);
        g_J[r * NSPIN + j] = v;
    }
    grid_barrier();     // only grid-wide barrier

    // ---- stage Js (valid for both gemms; rt fixed per block) ----
    for (int idx = tid; idx < 128 * 64; idx += 512) {
        int r = idx >> 6, k4 = (idx & 63) * 4;
        *(float4*)&Js[r * JS_STRIDE + k4] =
            *(const float4*)&g_J[(row0 + r) * NSPIN + k4];
    }
    // ---- stage As ----
    if (isH) {
        const float* A = x + (size_t)b * NSPIN * FDIM;
        for (int idx = tid; idx < 256 * 16; idx += 512) {
            int k = idx >> 4, c4 = idx & 15;
            *(float4*)&As[k * AS_STRIDE + c4 * 4] =
                *(const float4*)&A[(size_t)k * FDIM + c4 * 4];
        }
    } else {
        for (int idx = tid; idx < 256 * 16; idx += 512) {
            int k = idx >> 4, c4 = idx & 15;
            *(float4*)&As[k * AS_STRIDE + c4 * 4] =
                *(const float4*)&g_J[(size_t)k * NSPIN + col0 + c4 * 4];
        }
    }
    __syncthreads();

    const int ty = tid & 63;
    const int tx = tid >> 6;
    const float* jr0 = &Js[ty * JS_STRIDE];
    const float* jr1 = &Js[(ty + 64) * JS_STRIDE];
    const float* bcol = &As[tx * 8];

    if (isH) {
        // ================= H path =================
        // phase 1: u1 half = J_rows @ h
        unsigned long long acc[2][4];
        #pragma unroll
        for (int i = 0; i < 2; i++)
            #pragma unroll
            for (int j = 0; j < 4; j++) acc[i][j] = 0ull;
        gemm_range(jr0, jr1, bcol, 0, 256, acc);

        // epilogue: ac = <h_own, u1_own>, cc = ||u1_own||^2, aa = ||h_own||^2
        float ac = 0.f, cc = 0.f, aa = 0.f;
        float cv[2][8];
        #pragma unroll
        for (int i = 0; i < 2; i++) {
            cv[i][0] = lo32(acc[i][0]); cv[i][1] = hi32(acc[i][0]);
            cv[i][2] = lo32(acc[i][1]); cv[i][3] = hi32(acc[i][1]);
            cv[i][4] = lo32(acc[i][2]); cv[i][5] = hi32(acc[i][2]);
            cv[i][6] = lo32(acc[i][3]); cv[i][7] = hi32(acc[i][3]);
            int r = row0 + ty + 64 * i;
            const float* arow = &As[r * AS_STRIDE + tx * 8];
            #pragma unroll
            for (int j = 0; j < 8; j++) {
                ac += cv[i][j] * arow[j];
                cc += cv[i][j] * cv[i][j];
            }
        }
        for (int idx = tid; idx < 128 * 64; idx += 512) {     // own-half rows of h
            int k = row0 + (idx >> 6), c = idx & 63;
            float v = As[k * AS_STRIDE + c];
            aa += v * v;
        }
        float red;
        red = blockReduceSum(ac, scratch); if (tid == 0) g_mAC0[b][rt] = red;
        red = blockReduceSum(cc, scratch); if (tid == 0) g_mAA1[b][rt] = red;
        red = blockReduceSum(aa, scratch); if (tid == 0) g_mAA0[b][rt] = red;
        // (blockReduce ends with __syncthreads -> safe to overwrite As below)

        // store own u1 half: -> As (smem) and -> g_U1 (for partner)
        float* Cg = g_U1 + (size_t)b * NSPIN * FDIM;
        #pragma unroll
        for (int i = 0; i < 2; i++) {
            int r = row0 + ty + 64 * i;
            float* as = &As[r * AS_STRIDE + tx * 8];
            *(float4*)as       = make_float4(cv[i][0], cv[i][1], cv[i][2], cv[i][3]);
            *(float4*)(as + 4) = make_float4(cv[i][4], cv[i][5], cv[i][6], cv[i][7]);
            float* cg = &Cg[(size_t)r * FDIM + tx * 8];
            *(float4*)cg       = make_float4(cv[i][0], cv[i][1], cv[i][2], cv[i][3]);
            *(float4*)(cg + 4) = make_float4(cv[i][4], cv[i][5], cv[i][6], cv[i][7]);
        }
        __threadfence();
        __syncthreads();

        // arrive on pair ticket (no wait yet)
        unsigned tgt = 0;
        if (tid == 0) {
            unsigned old = atomicAdd(&g_pair[b], 1u);
            tgt = old - (old & 1u) + 2u;
        }

        // phase 2 first half: k over OWN u1 rows (fresh in As)
        #pragma unroll
        for (int i = 0; i < 2; i++)
            #pragma unroll
            for (int j = 0; j < 4; j++) acc[i][j] = 0ull;
        gemm_range(jr0, jr1, bcol, row0, row0 + 128, acc);

        // wait for partner, then load partner u1 half (L2, bypass L1)
        if (tid == 0)
            while ((int)(*(volatile unsigned*)&g_pair[b] - tgt) < 0) __nanosleep(32);
        __syncthreads();
        __threadfence();
        {
            const int prow0 = 128 - row0;
            for (int idx = tid; idx < 128 * 16; idx += 512) {
                int k = prow0 + (idx >> 4), c4 = (idx & 15) * 4;
                float4 v = __ldcg((const float4*)&Cg[(size_t)k * FDIM + c4]);
                *(float4*)&As[k * AS_STRIDE + c4] = v;
            }
        }
        __syncthreads();
        // phase 2 second half: k over partner rows
        {
            const int prow0 = 128 - row0;
            gemm_range(jr0, jr1, bcol, prow0, prow0 + 128, acc);
        }

        // epilogue: ac = <u1_own, u2_own>, cc = ||u2_own||^2
        ac = 0.f; cc = 0.f;
        #pragma unroll
        for (int i = 0; i < 2; i++) {
            int r = row0 + ty + 64 * i;
            float c0 = lo32(acc[i][0]), c1 = hi32(acc[i][0]);
            float c2 = lo32(acc[i][1]), c3 = hi32(acc[i][1]);
            float c4 = lo32(acc[i][2]), c5 = hi32(acc[i][2]);
            float c6 = lo32(acc[i][3]), c7 = hi32(acc[i][3]);
            const float* arow = &As[r * AS_STRIDE + tx * 8];
            ac += c0 * arow[0] + c1 * arow[1] + c2 * arow[2] + c3 * arow[3]
                + c4 * arow[4] + c5 * arow[5] + c6 * arow[6] + c7 * arow[7];
            cc += c0 * c0 + c1 * c1 + c2 * c2 + c3 * c3
                + c4 * c4 + c5 * c5 + c6 * c6 + c7 * c7;
        }
        red = blockReduceSum(ac, scratch); if (tid == 0) g_mAC1[b][rt] = red;
        red = blockReduceSum(cc, scratch); if (tid == 0) g_mCC [b][rt] = red;
    } else {
        // ================= matrix path (no mid sync) =================
        // tr(J^2) partial (rt==0 blocks: full col-slice)
        if (rt == 0) {
            float aa = 0.f;
            for (int idx = tid; idx < 256 * 64; idx += 512) {
                int k = idx >> 6, c = idx & 63;
                float v = As[k * AS_STRIDE + c];
                aa += v * v;
            }
            float aar = blockReduceSum(aa, scratch);
            if (tid == 0) g_tAA[ct] = aar;
        }
        // (J^2) tile in regs -> tr(J^3), tr(J^4) partials
        unsigned long long acc[2][4];
        #pragma unroll
        for (int i = 0; i < 2; i++)
            #pragma unroll
            for (int j = 0; j < 4; j++) acc[i][j] = 0ull;
        gemm_range(jr0, jr1, bcol, 0, 256, acc);
        float ac = 0.f, cc = 0.f;
        #pragma unroll
        for (int i = 0; i < 2; i++) {
            int r = row0 + ty + 64 * i;
            float c0 = lo32(acc[i][0]), c1 = hi32(acc[i][0]);
            float c2 = lo32(acc[i][1]), c3 = hi32(acc[i][1]);
            float c4 = lo32(acc[i][2]), c5 = hi32(acc[i][2]);
            float c6 = lo32(acc[i][3]), c7 = hi32(acc[i][3]);
            const float* arow = &As[r * AS_STRIDE + tx * 8];
            ac += c0 * arow[0] + c1 * arow[1] + c2 * arow[2] + c3 * arow[3]
                + c4 * arow[4] + c5 * arow[5] + c6 * arow[6] + c7 * arow[7];
            cc += c0 * c0 + c1 * c1 + c2 * c2 + c3 * c3
                + c4 * c4 + c5 * c5 + c6 * c6 + c7 * c7;
        }
        float red;
        red = blockReduceSum(ac, scratch); if (tid == 0) g_tAC[rt][ct] = red;
        red = blockReduceSum(cc, scratch); if (tid == 0) g_tCC[rt][ct] = red;
    }

    // ---- final arrival: last block runs fp32 Newton tail ----
    if (tid == 0) {
        islast = 0u;
        __threadfence();
        unsigned old = atomicAdd(&g_bar, 1u);
        if ((old % NBLK) == NBLK - 1u) islast = 1u;
    }
    __syncthreads();
    if (islast) {
        __threadfence();
        if (tid < BATCH) newton_tail(tid, out, out_size);
    }
}

// -------------------- launch --------------------
extern "C" void kernel_launch(void* const* d_in, const int* in_sizes, int n_in,
                              void* d_out, int out_size) {
    const float* x  = (const float*)d_in[0];   // (64, 256, 64)
    const float* Jr = (const float*)d_in[1];   // (256, 256)
    float* out = (float*)d_out;

    size_t shmem = (size_t)(128 * JS_STRIDE + 256 * AS_STRIDE) * sizeof(float);
    cudaFuncSetAttribute(fused_kernel, cudaFuncAttributeMaxDynamicSharedMemorySize,
                         (int)shmem);

    fused_kernel<<<NBLK, 512, shmem>>>(x, Jr, out, out_size);
}

// round 12
// speedup vs baseline: 1.0260x; 1.0260x over previous
#include <cuda_runtime.h>
#include <math.h>

#define NSPIN 256
#define FDIM  64
#define BATCH 64
#define NITER 40
#define TOLF  1e-4f
#define JS_STRIDE 260      // [128][260] floats: conflict-free LDS
#define AS_STRIDE 68       // [256][68] floats
#define NBLK   136u

// -------------------- device scratch (no runtime allocation) --------------------
__device__ float g_J[NSPIN * NSPIN];
__device__ float g_U1[BATCH * NSPIN * FDIM];            // J h (pair handoff)
__device__ float g_mAA0[BATCH][2];                      // ||h||^2 partials (by rt)
__device__ float g_mAC0[BATCH][2];                      // <h,u1> partials
__device__ float g_mAA1[BATCH][2];                      // ||u1||^2 partials
__device__ float g_mAC1[BATCH][2];                      // <u1,u2> partials
__device__ float g_mCC [BATCH][2];                      // ||u2||^2 partials
__device__ float g_tAA[4];                              // tr(J^2) partials (by ct)
__device__ float g_tAC[2][4];                           // tr(J^3) partials
__device__ float g_tCC[2][4];                           // tr(J^4) partials
__device__ unsigned g_bar;                              // monotonic grid ticket
__device__ unsigned g_pair[BATCH];                      // monotonic pair tickets

#define VL(x) (*(volatile float*)&(x))

// -------------------- helpers --------------------
__device__ __forceinline__ unsigned long long dup2(float a) {
    unsigned long long r;
    asm("mov.b64 %0, {%1, %1};" : "=l"(r) : "f"(a));
    return r;
}
__device__ __forceinline__ void fma2(unsigned long long& acc, unsigned long long a,
                                     unsigned long long b) {
    asm("fma.rn.f32x2 %0, %1, %2, %3;" : "=l"(acc) : "l"(a), "l"(b), "l"(acc));
}
__device__ __forceinline__ float lo32(unsigned long long v) {
    return __uint_as_float((unsigned)(v & 0xffffffffull));
}
__device__ __forceinline__ float hi32(unsigned long long v) {
    return __uint_as_float((unsigned)(v >> 32));
}

// grid-wide barrier: monotonic tickets, replay-safe. Valid: 136 blocks co-resident.
__device__ __forceinline__ void grid_barrier() {
    __threadfence();
    __syncthreads();
    if (threadIdx.x == 0) {
        unsigned old = atomicAdd(&g_bar, 1u);
        unsigned target = old - (old % NBLK) + NBLK;
        while ((int)(*(volatile unsigned*)&g_bar - target) < 0) __nanosleep(32);
    }
    __syncthreads();
}

// block reduce for 512 threads (16 warps)
__device__ __forceinline__ float blockReduceSum(float v, float* scratch) {
    #pragma unroll
    for (int o = 16; o > 0; o >>= 1) v += __shfl_down_sync(0xffffffffu, v, o);
    int lane = threadIdx.x & 31, w = threadIdx.x >> 5;
    if (lane == 0) scratch[w] = v;
    __syncthreads();
    float r = 0.f;
    if (w == 0) {
        r = (lane < 16) ? scratch[lane] : 0.f;
        #pragma unroll
        for (int o = 8; o > 0; o >>= 1) r += __shfl_down_sync(0xffffffffu, r, o);
    }
    __syncthreads();
    return r;   // valid in thread 0
}

// -------------------- inner gemm over k range [k0,k1), accumulating ------------
__device__ __forceinline__ void gemm_range(const float* jr0, const float* jr1,
                                           const float* bcol, int k0, int k1,
                                           unsigned long long acc[2][4]) {
    #pragma unroll 4
    for (int kk = k0; kk < k1; kk += 4) {
        float4 ja = *(const float4*)&jr0[kk];
        float4 jb = *(const float4*)&jr1[kk];
        #pragma unroll
        for (int u = 0; u < 4; ++u) {
            ulonglong2 b0 = *(const ulonglong2*)&bcol[(kk + u) * AS_STRIDE];
            ulonglong2 b1 = *(const ulonglong2*)&bcol[(kk + u) * AS_STRIDE + 4];
            float jav = (u == 0) ? ja.x : (u == 1) ? ja.y : (u == 2) ? ja.z : ja.w;
            float jbv = (u == 0) ? jb.x : (u == 1) ? jb.y : (u == 2) ? jb.z : jb.w;
            unsigned long long a0 = dup2(jav);
            unsigned long long a1 = dup2(jbv);
            fma2(acc[0][0], a0, b0.x); fma2(acc[0][1], a0, b0.y);
            fma2(acc[0][2], a0, b1.x); fma2(acc[0][3], a0, b1.y);
            fma2(acc[1][0], a1, b0.x); fma2(acc[1][1], a1, b0.y);
            fma2(acc[1][2], a1, b1.x); fma2(acc[1][3], a1, b1.y);
        }
    }
}

// -------------------- fp32 Newton + phi + afe tail (last arrival) --------------
__device__ void newton_tail(int b, float* out, int out_size) {
    float m0 = VL(g_mAA0[b][0]) + VL(g_mAA0[b][1]);
    float m1 = VL(g_mAC0[b][0]) + VL(g_mAC0[b][1]);
    float m2 = VL(g_mAA1[b][0]) + VL(g_mAA1[b][1]);
    float m3 = VL(g_mAC1[b][0]) + VL(g_mAC1[b][1]);
    float m4 = VL(g_mCC [b][0]) + VL(g_mCC [b][1]);

    float tp2 = 0.f, tp3 = 0.f, tp4 = 0.f;
    #pragma unroll
    for (int q = 0; q < 4; q++) tp2 += VL(g_tAA[q]);
    #pragma unroll
    for (int r = 0; r < 2; r++)
        #pragma unroll
        for (int q = 0; q < 4; q++) { tp3 += VL(g_tAC[r][q]); tp4 += VL(g_tCC[r][q]); }

    const float cSb2 = 3.f * tp2, cSb3 = 4.f * tp3, cSb4 = 5.f * tp4;
    const float cQb0 = m0, cQb1 = 2.f*m1, cQb2 = 3.f*m2, cQb3 = 4.f*m3, cQb4 = 5.f*m4;
    const float cQc0 = m0, cQc1 = 3.f*m1, cQc2 = 6.f*m2, cQc3 = 10.f*m3, cQc4 = 15.f*m4;

    float t = 1.0f;
    for (int it = 0; it < NITER; ++it) {
        float xv = 1.0f / t;
        float Sa = (((tp4 * xv + tp3) * xv + tp2) * xv) * xv + 256.f;
        float Sb = (((cSb4 * xv + cSb3) * xv + cSb2) * xv) * xv + 256.f;
        float Qb = (((cQb4 * xv + cQb3) * xv + cQb2) * xv + cQb1) * xv + cQb0;
        float Qc = (((cQc4 * xv + cQc3) * xv + cQc2) * xv + cQc1) * xv + cQc0;
        float s1 = xv * Sa;
        float s2 = xv * xv * Sb;
        float q2 = xv * xv * Qb;
        float q3 = xv * xv * xv * Qc;
        float g  = 256.f - 0.5f * s1 - q2 * (1.f / 256.f);
        if (fabsf(g) <= TOLF) break;      // reference's update is 0 from here on
        float gp = 0.5f * s2 + q3 * (1.f / 128.f);
        t -= g / gp;
    }

    float xv = 1.0f / t;
    float Qa = ((((m4 * xv + m3) * xv + m2) * xv + m1) * xv + m0);
    float q1 = xv * Qa;
    float lds = ((tp4 * 0.25f * xv + tp3 * (1.f / 3.f)) * xv + tp2 * 0.5f) * xv * xv;
    float logdet = 256.f * __logf(t) - lds;
    float phi = 256.f * t - 0.5f * logdet + q1 * (1.f / 256.f);
    float afe = -(0.57236494292f + phi * (1.f / 256.f));   // 0.5*log(pi) + phi/N

    out[b] = afe;
    if (out_size >= 2 * BATCH) out[BATCH + b] = t;
}

// -------------------- the single fused kernel ----------------------------------
__global__ void __launch_bounds__(512, 1)
fused_kernel(const float* __restrict__ x, const float* __restrict__ Jr,
             float* __restrict__ out, int out_size) {
    extern __shared__ float sh[];
    float* Js = sh;                               // [128][JS_STRIDE]
    float* As = sh + 128 * JS_STRIDE;             // [256][AS_STRIDE]
    __shared__ float scratch[16];
    __shared__ unsigned islast;

    const int bid = blockIdx.x;
    const int tid = threadIdx.x;
    const bool isH = (bid < 128);

    int b = 0, rt, ct;
    if (isH) { b = bid >> 1; rt = bid & 1; ct = 0; }
    else     { int t = bid - 128; rt = t >> 2; ct = t & 3; }
    const int row0 = rt * 128;
    const int col0 = ct * 64;

    // ---- phase 0: build J once, cooperatively (2 rows per H block) ----
    if (isH) {
        int r = bid * 2 + (tid >> 8);
        int j = tid & 255;
        float v = (r == j) ? 0.f : 0.5f * (Jr[r * NSPIN + j] + Jr[j * NSPIN + r]);
        g_J[r * NSPIN + j] = v;
    }
    grid_barrier();     // only grid-wide barrier

    // ---- stage Js (valid for both gemms; rt fixed per block) ----
    for (int idx = tid; idx < 128 * 64; idx += 512) {
        int r = idx >> 6, k4 = (idx & 63) * 4;
        *(float4*)&Js[r * JS_STRIDE + k4] =
            *(const float4*)&g_J[(row0 + r) * NSPIN + k4];
    }
    // ---- stage As ----
    if (isH) {
        const float* A = x + (size_t)b * NSPIN * FDIM;
        for (int idx = tid; idx < 256 * 16; idx += 512) {
            int k = idx >> 4, c4 = idx & 15;
            *(float4*)&As[k * AS_STRIDE + c4 * 4] =
                *(const float4*)&A[(size_t)k * FDIM + c4 * 4];
        }
    } else {
        for (int idx = tid; idx < 256 * 16; idx += 512) {
            int k = idx >> 4, c4 = idx & 15;
            *(float4*)&As[k * AS_STRIDE + c4 * 4] =
                *(const float4*)&g_J[(size_t)k * NSPIN + col0 + c4 * 4];
        }
    }
    __syncthreads();

    const int ty = tid & 63;
    const int tx = tid >> 6;
    const float* jr0 = &Js[ty * JS_STRIDE];
    const float* jr1 = &Js[(ty + 64) * JS_STRIDE];
    const float* bcol = &As[tx * 8];

    if (isH) {
        // ================= H path =================
        // phase 1: u1 half = J_rows @ h
        unsigned long long acc[2][4];
        #pragma unroll
        for (int i = 0; i < 2; i++)
            #pragma unroll
            for (int j = 0; j < 4; j++) acc[i][j] = 0ull;
        gemm_range(jr0, jr1, bcol, 0, 256, acc);

        // epilogue: ac = <h_own, u1_own>, cc = ||u1_own||^2, aa = ||h_own||^2
        float ac = 0.f, cc = 0.f, aa = 0.f;
        float cv[2][8];
        #pragma unroll
        for (int i = 0; i < 2; i++) {
            cv[i][0] = lo32(acc[i][0]); cv[i][1] = hi32(acc[i][0]);
            cv[i][2] = lo32(acc[i][1]); cv[i][3] = hi32(acc[i][1]);
            cv[i][4] = lo32(acc[i][2]); cv[i][5] = hi32(acc[i][2]);
            cv[i][6] = lo32(acc[i][3]); cv[i][7] = hi32(acc[i][3]);
            int r = row0 + ty + 64 * i;
            const float* arow = &As[r * AS_STRIDE + tx * 8];
            #pragma unroll
            for (int j = 0; j < 8; j++) {
                ac += cv[i][j] * arow[j];
                cc += cv[i][j] * cv[i][j];
            }
        }
        for (int idx = tid; idx < 128 * 64; idx += 512) {     // own-half rows of h
            int k = row0 + (idx >> 6), c = idx & 63;
            float v = As[k * AS_STRIDE + c];
            aa += v * v;
        }
        float red;
        red = blockReduceSum(ac, scratch); if (tid == 0) g_mAC0[b][rt] = red;
        red = blockReduceSum(cc, scratch); if (tid == 0) g_mAA1[b][rt] = red;
        red = blockReduceSum(aa, scratch); if (tid == 0) g_mAA0[b][rt] = red;
        // (blockReduce ends with __syncthreads -> safe to overwrite As below)

        // store own u1 half: -> As (smem) and -> g_U1 (for partner)
        float* Cg = g_U1 + (size_t)b * NSPIN * FDIM;
        #pragma unroll
        for (int i = 0; i < 2; i++) {
            int r = row0 + ty + 64 * i;
            float* as = &As[r * AS_STRIDE + tx * 8];
            *(float4*)as       = make_float4(cv[i][0], cv[i][1], cv[i][2], cv[i][3]);
            *(float4*)(as + 4) = make_float4(cv[i][4], cv[i][5], cv[i][6], cv[i][7]);
            float* cg = &Cg[(size_t)r * FDIM + tx * 8];
            *(float4*)cg       = make_float4(cv[i][0], cv[i][1], cv[i][2], cv[i][3]);
            *(float4*)(cg + 4) = make_float4(cv[i][4], cv[i][5], cv[i][6], cv[i][7]);
        }
        __threadfence();
        __syncthreads();

        // arrive on pair ticket (no wait yet)
        unsigned tgt = 0;
        if (tid == 0) {
            unsigned old = atomicAdd(&g_pair[b], 1u);
            tgt = old - (old & 1u) + 2u;
        }

        // phase 2 first half: k over OWN u1 rows (fresh in As)
        #pragma unroll
        for (int i = 0; i < 2; i++)
            #pragma unroll
            for (int j = 0; j < 4; j++) acc[i][j] = 0ull;
        gemm_range(jr0, jr1, bcol, row0, row0 + 128, acc);

        // wait for partner, then load partner u1 half (L2, bypass L1)
        if (tid == 0)
            while ((int)(*(volatile unsigned*)&g_pair[b] - tgt) < 0) __nanosleep(32);
        __syncthreads();
        __threadfence();
        {
            const int prow0 = 128 - row0;
            for (int idx = tid; idx < 128 * 16; idx += 512) {
                int k = prow0 + (idx >> 4), c4 = (idx & 15) * 4;
                float4 v = __ldcg((const float4*)&Cg[(size_t)k * FDIM + c4]);
                *(float4*)&As[k * AS_STRIDE + c4] = v;
            }
        }
        __syncthreads();
        // phase 2 second half: k over partner rows
        {
            const int prow0 = 128 - row0;
            gemm_range(jr0, jr1, bcol, prow0, prow0 + 128, acc);
        }

        // epilogue: ac = <u1_own, u2_own>, cc = ||u2_own||^2
        ac = 0.f; cc = 0.f;
        #pragma unroll
        for (int i = 0; i < 2; i++) {
            int r = row0 + ty + 64 * i;
            float c0 = lo32(acc[i][0]), c1 = hi32(acc[i][0]);
            float c2 = lo32(acc[i][1]), c3 = hi32(acc[i][1]);
            float c4 = lo32(acc[i][2]), c5 = hi32(acc[i][2]);
            float c6 = lo32(acc[i][3]), c7 = hi32(acc[i][3]);
            const float* arow = &As[r * AS_STRIDE + tx * 8];
            ac += c0 * arow[0] + c1 * arow[1] + c2 * arow[2] + c3 * arow[3]
                + c4 * arow[4] + c5 * arow[5] + c6 * arow[6] + c7 * arow[7];
            cc += c0 * c0 + c1 * c1 + c2 * c2 + c3 * c3
                + c4 * c4 + c5 * c5 + c6 * c6 + c7 * c7;
        }
        red = blockReduceSum(ac, scratch); if (tid == 0) g_mAC1[b][rt] = red;
        red = blockReduceSum(cc, scratch); if (tid == 0) g_mCC [b][rt] = red;
    } else {
        // ================= matrix path (no mid sync) =================
        // tr(J^2) partial (rt==0 blocks: full col-slice)
        if (rt == 0) {
            float aa = 0.f;
            for (int idx = tid; idx < 256 * 64; idx += 512) {
                int k = idx >> 6, c = idx & 63;
                float v = As[k * AS_STRIDE + c];
                aa += v * v;
            }
            float aar = blockReduceSum(aa, scratch);
            if (tid == 0) g_tAA[ct] = aar;
        }
        // (J^2) tile in regs -> tr(J^3), tr(J^4) partials
        unsigned long long acc[2][4];
        #pragma unroll
        for (int i = 0; i < 2; i++)
            #pragma unroll
            for (int j = 0; j < 4; j++) acc[i][j] = 0ull;
        gemm_range(jr0, jr1, bcol, 0, 256, acc);
        float ac = 0.f, cc = 0.f;
        #pragma unroll
        for (int i = 0; i < 2; i++) {
            int r = row0 + ty + 64 * i;
            float c0 = lo32(acc[i][0]), c1 = hi32(acc[i][0]);
            float c2 = lo32(acc[i][1]), c3 = hi32(acc[i][1]);
            float c4 = lo32(acc[i][2]), c5 = hi32(acc[i][2]);
            float c6 = lo32(acc[i][3]), c7 = hi32(acc[i][3]);
            const float* arow = &As[r * AS_STRIDE + tx * 8];
            ac += c0 * arow[0] + c1 * arow[1] + c2 * arow[2] + c3 * arow[3]
                + c4 * arow[4] + c5 * arow[5] + c6 * arow[6] + c7 * arow[7];
            cc += c0 * c0 + c1 * c1 + c2 * c2 + c3 * c3
                + c4 * c4 + c5 * c5 + c6 * c6 + c7 * c7;
        }
        float red;
        red = blockReduceSum(ac, scratch); if (tid == 0) g_tAC[rt][ct] = red;
        red = blockReduceSum(cc, scratch); if (tid == 0) g_tCC[rt][ct] = red;
    }

    // ---- final arrival: last block runs fp32 Newton tail ----
    if (tid == 0) {
        islast = 0u;
        __threadfence();
        unsigned old = atomicAdd(&g_bar, 1u);
        if ((old % NBLK) == NBLK - 1u) islast = 1u;
    }
    __syncthreads();
    if (islast) {
        __threadfence();
        if (tid < BATCH) newton_tail(tid, out, out_size);
    }
}

// -------------------- launch --------------------
extern "C" void kernel_launch(void* const* d_in, const int* in_sizes, int n_in,
                              void* d_out, int out_size) {
    const float* x  = (const float*)d_in[0];   // (64, 256, 64)
    const float* Jr = (const float*)d_in[1];   // (256, 256)
    float* out = (float*)d_out;

    size_t shmem = (size_t)(128 * JS_STRIDE + 256 * AS_STRIDE) * sizeof(float);
    cudaFuncSetAttribute(fused_kernel, cudaFuncAttributeMaxDynamicSharedMemorySize,
                         (int)shmem);

    fused_kernel<<<NBLK, 512, shmem>>>(x, Jr, out, out_size);
}